// round 3
// baseline (speedup 1.0000x reference)
#include <cuda_runtime.h>

#define N_VERTS 53215
#define EXP_DIM 29
#define SHP_DIM 199
#define SHP3    (3 * SHP_DIM)   // 597
#define EXP3    (3 * EXP_DIM)   // 87

#define NBLOCKS 592             // ~one wave at 4 blocks/SM on 148 SMs
#define NTHREADS 256

// ---------------------------------------------------------------------------
// Persistent warp-per-vertex fused kernel with alpha registers hoisted.
//
// Per-lane alpha columns depend only on (pass index i, lane) — identical for
// every vertex. Each warp preloads its 19 shp-alpha + 3 exp-alpha values into
// registers once, then grid-strides over vertices doing only the streaming
// w loads (evict-first) + FMAs + reduction + closed-form transform.
//
// Transform (derived from _transform_matrix(pose, 450)):
//   s  = p3 + p7 + p11
//   ox = ( s*(p0x + p1y + p2z)  + p3)        * (224/450)
//   oy = (-s*(p4x + p5y + p6z)  - p7 + 450)  * (224/450)
//   oz =   s*(p8x + p9y + p10z)
// ---------------------------------------------------------------------------
__global__ void __launch_bounds__(NTHREADS)
pca_fused_kernel(const float* __restrict__ pose,
                 const float* __restrict__ a_exp,
                 const float* __restrict__ a_shp,
                 const float* __restrict__ u,
                 const float* __restrict__ w_exp,
                 const float* __restrict__ w_shp,
                 float* __restrict__ out)
{
    const int lane       = threadIdx.x & 31;
    const int warp_gid   = (blockIdx.x * blockDim.x + threadIdx.x) >> 5;
    const int total_warps = (NBLOCKS * NTHREADS) >> 5;

    // ---- hoist alpha values: fixed per lane, shared by all vertices ----
    float as[19];
    #pragma unroll
    for (int i = 0; i < 19; i++) {
        const int j = i * 32 + lane;
        as[i] = (j < SHP3) ? __ldg(a_shp + (j % SHP_DIM)) : 0.0f;
    }
    float ae[3];
    #pragma unroll
    for (int i = 0; i < 3; i++) {
        const int j = i * 32 + lane;
        ae[i] = (j < EXP3) ? __ldg(a_exp + (j % EXP_DIM)) : 0.0f;
    }

    // ---- hoist pose / transform coefficients ----
    const float p0 = __ldg(pose + 0),  p1 = __ldg(pose + 1),  p2  = __ldg(pose + 2),  p3  = __ldg(pose + 3);
    const float p4 = __ldg(pose + 4),  p5 = __ldg(pose + 5),  p6  = __ldg(pose + 6),  p7  = __ldg(pose + 7);
    const float p8 = __ldg(pose + 8),  p9 = __ldg(pose + 9),  p10 = __ldg(pose + 10), p11 = __ldg(pose + 11);
    const float s  = p3 + p7 + p11;
    const float aspect_xy = 224.0f / 450.0f;

    // ---- grid-stride over vertices ----
    for (int v = warp_gid; v < N_VERTS; v += total_warps) {
        const float* __restrict__ ws = w_shp + (size_t)v * SHP3;
        const float* __restrict__ we = w_exp + (size_t)v * EXP3;

        float acc0 = 0.0f, acc1 = 0.0f, acc2 = 0.0f;

        // SHP block: 597 contiguous floats, 19 coalesced passes (last partial)
        #pragma unroll
        for (int i = 0; i < 19; i++) {
            const int j = i * 32 + lane;
            if (j < SHP3) {
                const float p = __ldcs(ws + j) * as[i];
                if (j < SHP_DIM)          acc0 += p;
                else if (j < 2 * SHP_DIM) acc1 += p;
                else                      acc2 += p;
            }
        }

        // EXP block: 87 contiguous floats, 3 coalesced passes (last partial)
        #pragma unroll
        for (int i = 0; i < 3; i++) {
            const int j = i * 32 + lane;
            if (j < EXP3) {
                const float p = __ldcs(we + j) * ae[i];
                if (j < EXP_DIM)          acc0 += p;
                else if (j < 2 * EXP_DIM) acc1 += p;
                else                      acc2 += p;
            }
        }

        // warp reductions (3 values)
        #pragma unroll
        for (int off = 16; off > 0; off >>= 1) {
            acc0 += __shfl_down_sync(0xffffffffu, acc0, off);
            acc1 += __shfl_down_sync(0xffffffffu, acc1, off);
            acc2 += __shfl_down_sync(0xffffffffu, acc2, off);
        }

        if (lane == 0) {
            const float x = acc0 + __ldg(u + 3 * v + 0);
            const float y = acc1 + __ldg(u + 3 * v + 1);
            const float z = acc2 + __ldg(u + 3 * v + 2);

            out[3 * v + 0] = ( s * (p0 * x + p1 * y + p2  * z) + p3)          * aspect_xy;
            out[3 * v + 1] = (-s * (p4 * x + p5 * y + p6  * z) - p7 + 450.0f) * aspect_xy;
            out[3 * v + 2] =   s * (p8 * x + p9 * y + p10 * z);
        }
    }
}

// ---------------------------------------------------------------------------
// Entry point
// Input order: pose_3DMM, alpha_exp, alpha_shp, u_base, w_exp_base, w_shp_base
// ---------------------------------------------------------------------------
extern "C" void kernel_launch(void* const* d_in, const int* in_sizes, int n_in,
                              void* d_out, int out_size)
{
    const float* pose  = (const float*)d_in[0];
    const float* a_exp = (const float*)d_in[1];
    const float* a_shp = (const float*)d_in[2];
    const float* u     = (const float*)d_in[3];
    const float* w_exp = (const float*)d_in[4];
    const float* w_shp = (const float*)d_in[5];
    float* out = (float*)d_out;

    pca_fused_kernel<<<NBLOCKS, NTHREADS>>>(pose, a_exp, a_shp, u, w_exp, w_shp, out);
}

// round 4
// speedup vs baseline: 1.1096x; 1.1096x over previous
#include <cuda_runtime.h>

#define N_VERTS 53215
#define EXP_DIM 29
#define SHP_DIM 199
#define SHP3    (3 * SHP_DIM)   // 597
#define EXP3    (3 * EXP_DIM)   // 87

#define NTHREADS 256
#define WARPS_PER_BLOCK (NTHREADS / 32)
#define N_PAIRS  ((N_VERTS + 1) / 2)         // 26608

// ---------------------------------------------------------------------------
// Warp-per-2-vertices fused kernel (R2 geometry + hoisted alphas).
//
// Each warp handles vertices v0=2p, v1=2p+1. The 22 per-lane alpha values are
// loaded ONCE per warp into registers (they depend only on lane), then both
// vertices' contiguous w-blocks are streamed interleaved (high MLP) with
// compile-time row routing into 6 accumulators. 6 warp reductions, closed-form
// transform, direct store.
//
// Transform (derived from _transform_matrix(pose, 450)):
//   s  = p3 + p7 + p11
//   ox = ( s*(p0x + p1y + p2z)  + p3)        * (224/450)
//   oy = (-s*(p4x + p5y + p6z)  - p7 + 450)  * (224/450)
//   oz =   s*(p8x + p9y + p10z)
// ---------------------------------------------------------------------------
__global__ void __launch_bounds__(NTHREADS)
pca_fused2_kernel(const float* __restrict__ pose,
                  const float* __restrict__ a_exp,
                  const float* __restrict__ a_shp,
                  const float* __restrict__ u,
                  const float* __restrict__ w_exp,
                  const float* __restrict__ w_shp,
                  float* __restrict__ out)
{
    const int pair = (blockIdx.x * blockDim.x + threadIdx.x) >> 5;
    const int lane = threadIdx.x & 31;
    if (pair >= N_PAIRS) return;

    const int v0 = 2 * pair;
    const int v1 = v0 + 1;
    const bool has_v1 = (v1 < N_VERTS);
    const int v1c = has_v1 ? v1 : v0;        // clamp loads; store guarded

    // ---- hoist alphas (lane-dependent only, shared by both vertices) ----
    float as[19];
    #pragma unroll
    for (int i = 0; i < 19; i++) {
        const int j = i * 32 + lane;
        as[i] = (j < SHP3) ? __ldg(a_shp + (j % SHP_DIM)) : 0.0f;
    }
    float ae[3];
    #pragma unroll
    for (int i = 0; i < 3; i++) {
        const int j = i * 32 + lane;
        ae[i] = (j < EXP3) ? __ldg(a_exp + (j % EXP_DIM)) : 0.0f;
    }

    const float* __restrict__ ws0 = w_shp + (size_t)v0  * SHP3;
    const float* __restrict__ ws1 = w_shp + (size_t)v1c * SHP3;
    const float* __restrict__ we0 = w_exp + (size_t)v0  * EXP3;
    const float* __restrict__ we1 = w_exp + (size_t)v1c * EXP3;

    float a0x = 0.f, a0y = 0.f, a0z = 0.f;
    float a1x = 0.f, a1y = 0.f, a1z = 0.f;

    // ---- SHP blocks: 597 floats each, interleaved streaming ----
    #pragma unroll
    for (int i = 0; i < 19; i++) {
        const int j = i * 32 + lane;
        if (j < SHP3) {
            const float w0 = ws0[j];
            const float w1 = ws1[j];
            const float q0 = w0 * as[i];
            const float q1 = w1 * as[i];
            if (j < SHP_DIM)          { a0x += q0; a1x += q1; }
            else if (j < 2 * SHP_DIM) { a0y += q0; a1y += q1; }
            else                      { a0z += q0; a1z += q1; }
        }
    }

    // ---- EXP blocks: 87 floats each ----
    #pragma unroll
    for (int i = 0; i < 3; i++) {
        const int j = i * 32 + lane;
        if (j < EXP3) {
            const float w0 = we0[j];
            const float w1 = we1[j];
            const float q0 = w0 * ae[i];
            const float q1 = w1 * ae[i];
            if (j < EXP_DIM)          { a0x += q0; a1x += q1; }
            else if (j < 2 * EXP_DIM) { a0y += q0; a1y += q1; }
            else                      { a0z += q0; a1z += q1; }
        }
    }

    // ---- warp reductions (6 values) ----
    #pragma unroll
    for (int off = 16; off > 0; off >>= 1) {
        a0x += __shfl_down_sync(0xffffffffu, a0x, off);
        a0y += __shfl_down_sync(0xffffffffu, a0y, off);
        a0z += __shfl_down_sync(0xffffffffu, a0z, off);
        a1x += __shfl_down_sync(0xffffffffu, a1x, off);
        a1y += __shfl_down_sync(0xffffffffu, a1y, off);
        a1z += __shfl_down_sync(0xffffffffu, a1z, off);
    }

    if (lane == 0) {
        const float p0 = __ldg(pose + 0),  p1 = __ldg(pose + 1),  p2  = __ldg(pose + 2),  p3  = __ldg(pose + 3);
        const float p4 = __ldg(pose + 4),  p5 = __ldg(pose + 5),  p6  = __ldg(pose + 6),  p7  = __ldg(pose + 7);
        const float p8 = __ldg(pose + 8),  p9 = __ldg(pose + 9),  p10 = __ldg(pose + 10), p11 = __ldg(pose + 11);
        const float s  = p3 + p7 + p11;
        const float aspect_xy = 224.0f / 450.0f;

        {
            const float x = a0x + __ldg(u + 3 * v0 + 0);
            const float y = a0y + __ldg(u + 3 * v0 + 1);
            const float z = a0z + __ldg(u + 3 * v0 + 2);
            out[3 * v0 + 0] = ( s * (p0 * x + p1 * y + p2  * z) + p3)          * aspect_xy;
            out[3 * v0 + 1] = (-s * (p4 * x + p5 * y + p6  * z) - p7 + 450.0f) * aspect_xy;
            out[3 * v0 + 2] =   s * (p8 * x + p9 * y + p10 * z);
        }
        if (has_v1) {
            const float x = a1x + __ldg(u + 3 * v1 + 0);
            const float y = a1y + __ldg(u + 3 * v1 + 1);
            const float z = a1z + __ldg(u + 3 * v1 + 2);
            out[3 * v1 + 0] = ( s * (p0 * x + p1 * y + p2  * z) + p3)          * aspect_xy;
            out[3 * v1 + 1] = (-s * (p4 * x + p5 * y + p6  * z) - p7 + 450.0f) * aspect_xy;
            out[3 * v1 + 2] =   s * (p8 * x + p9 * y + p10 * z);
        }
    }
}

// ---------------------------------------------------------------------------
// Entry point
// Input order: pose_3DMM, alpha_exp, alpha_shp, u_base, w_exp_base, w_shp_base
// ---------------------------------------------------------------------------
extern "C" void kernel_launch(void* const* d_in, const int* in_sizes, int n_in,
                              void* d_out, int out_size)
{
    const float* pose  = (const float*)d_in[0];
    const float* a_exp = (const float*)d_in[1];
    const float* a_shp = (const float*)d_in[2];
    const float* u     = (const float*)d_in[3];
    const float* w_exp = (const float*)d_in[4];
    const float* w_shp = (const float*)d_in[5];
    float* out = (float*)d_out;

    const int blocks = (N_PAIRS + WARPS_PER_BLOCK - 1) / WARPS_PER_BLOCK;
    pca_fused2_kernel<<<blocks, NTHREADS>>>(pose, a_exp, a_shp, u, w_exp, w_shp, out);
}